// round 8
// baseline (speedup 1.0000x reference)
#include <cuda_runtime.h>
#include <math.h>

// TsCv: sliding-window coefficient of variation.
// x: (64, 256, 4096) fp32  -> out: (64, 256, 816) fp32
// window = 20, stride = 5, var ddof=1, cv = std/(mean+1e-8), NaN -> 0.
//
// Numerics: ONLY the window SUM must bit-match the reference (XLA:GPU
// warp-shuffle tree, shfl_down 16,8,4,2,1 with zero lanes 20..31):
//   A_j = ((w_j + w_{16+j}) + w_{8+j}) + (w_{4+j} + w_{12+j})   j=0..3
//   sum = (A0 + A2) + (A1 + A3)
// Everything downstream (mean, var, sqrt, div) only needs RELATIVE accuracy
// ~1e-6 (threshold 1e-3, verified margin), so we use the sumsq identity
// ssd = sum(w^2) - sum*mean and fast approx sqrt/div to halve instruction count.

#define SEQ_LEN   4096
#define MIN_W     20
#define STRIDE_W  5
#define OUT_LEN   ((SEQ_LEN - MIN_W) / STRIDE_W + 1)   // 816
#define EPS_CV    1e-8f
#define BLOCK_T   272        // 816 / 3 windows per thread
#define WPT       3

__device__ __forceinline__ float warp_tree_sum20(const float* __restrict__ w)
{
    float A0 = __fadd_rn(__fadd_rn(__fadd_rn(w[0], w[16]), w[8]),
                         __fadd_rn(w[4], w[12]));
    float A1 = __fadd_rn(__fadd_rn(__fadd_rn(w[1], w[17]), w[9]),
                         __fadd_rn(w[5], w[13]));
    float A2 = __fadd_rn(__fadd_rn(__fadd_rn(w[2], w[18]), w[10]),
                         __fadd_rn(w[6], w[14]));
    float A3 = __fadd_rn(__fadd_rn(__fadd_rn(w[3], w[19]), w[11]),
                         __fadd_rn(w[7], w[15]));
    return __fadd_rn(__fadd_rn(A0, A2), __fadd_rn(A1, A3));
}

__global__ __launch_bounds__(BLOCK_T)
void TsCv_29257317220818_kernel(const float* __restrict__ x,
                                float* __restrict__ out)
{
    __shared__ float row[SEQ_LEN];

    const int r = blockIdx.x;                 // flattened (b, f) row index
    const float* __restrict__ src = x + (size_t)r * SEQ_LEN;

    // Coalesced vectorized row load: 4096 floats = 1024 float4.
    const float4* __restrict__ src4 = (const float4*)src;
    float4* row4 = (float4*)row;
    for (int i = threadIdx.x; i < SEQ_LEN / 4; i += BLOCK_T) {
        row4[i] = src4[i];
    }
    __syncthreads();

    // Each thread: 3 consecutive windows, one 30-float span.
    // Lane address stride = 15 words, coprime with 32 banks -> conflict-free.
    const int o0 = threadIdx.x * WPT;
    const int s0 = o0 * STRIDE_W;

    float w[MIN_W + (WPT - 1) * STRIDE_W];    // 30 floats
    #pragma unroll
    for (int k = 0; k < MIN_W + (WPT - 1) * STRIDE_W; k++) {
        w[k] = row[s0 + k];
    }

    float* __restrict__ dst = out + (size_t)r * OUT_LEN + o0;

    #pragma unroll
    for (int j = 0; j < WPT; j++) {
        const float* ww = w + j * STRIDE_W;

        // Bit-exact reference sum (warp-shuffle tree order).
        const float sum  = warp_tree_sum20(ww);
        const float mean = sum * 0.05f;

        // Sum of squares via FMA chain (order-free; relative accuracy only).
        float sumsq = 0.0f;
        #pragma unroll
        for (int k = 0; k < MIN_W; k++) {
            sumsq = fmaf(ww[k], ww[k], sumsq);
        }
        // ssd = sum(w^2) - 20*mean^2 = sumsq - sum*mean
        const float ssd = fmaf(-sum, mean, sumsq);
        float var = ssd * (1.0f / (MIN_W - 1));
        var = fmaxf(var, 0.0f);               // guard approx-rounding negatives

        float sd;
        asm("sqrt.approx.f32 %0, %1;" : "=f"(sd) : "f"(var));
        const float den = mean + EPS_CV;
        float cv = __fdividef(sd, den);
        if (isnan(cv)) cv = 0.0f;
        dst[j] = cv;
    }
}

extern "C" void kernel_launch(void* const* d_in, const int* in_sizes, int n_in,
                              void* d_out, int out_size)
{
    const float* x = (const float*)d_in[0];
    float* out = (float*)d_out;

    const int n_rows = in_sizes[0] / SEQ_LEN;   // 64 * 256 = 16384
    TsCv_29257317220818_kernel<<<n_rows, BLOCK_T>>>(x, out);
}

// round 12
// speedup vs baseline: 1.4099x; 1.4099x over previous
#include <cuda_runtime.h>
#include <cstdint>
#include <math.h>

// TsCv: sliding-window coefficient of variation.
// x: (64, 256, 4096) fp32  -> out: (64, 256, 816) fp32
// window = 20, stride = 5, var ddof=1, cv = std/(mean+1e-8), NaN -> 0.
//
// Numerics: ONLY the window SUM must bit-match the reference (XLA:GPU
// warp-shuffle tree, shfl_down 16,8,4,2,1 with zero lanes 20..31).
// Downstream math needs only ~1e-6 relative accuracy (threshold 1e-3):
// sumsq identity + approx sqrt/div (validated in R7: rel_err 9.8e-8).
//
// Perf: R7 showed dur == 310MB / 4.3TB/s exactly -> achieved-BW bound, not
// ceiling-bound. This version pipelines: each CTA handles 8 consecutive rows,
// double-buffered via cp.async (load row i+1 while computing row i), keeping
// a continuous DRAM stream per SM and amortizing CTA head/tail latency.

#define SEQ_LEN   4096
#define MIN_W     20
#define STRIDE_W  5
#define OUT_LEN   ((SEQ_LEN - MIN_W) / STRIDE_W + 1)   // 816
#define EPS_CV    1e-8f
#define BLOCK_T   256
#define ROWS_PER_CTA 8
#define VEC_PER_ROW  (SEQ_LEN / 4)                     // 1024 float4

__device__ __forceinline__ float warp_tree_sum20(const float* __restrict__ w)
{
    float A0 = __fadd_rn(__fadd_rn(__fadd_rn(w[0], w[16]), w[8]),
                         __fadd_rn(w[4], w[12]));
    float A1 = __fadd_rn(__fadd_rn(__fadd_rn(w[1], w[17]), w[9]),
                         __fadd_rn(w[5], w[13]));
    float A2 = __fadd_rn(__fadd_rn(__fadd_rn(w[2], w[18]), w[10]),
                         __fadd_rn(w[6], w[14]));
    float A3 = __fadd_rn(__fadd_rn(__fadd_rn(w[3], w[19]), w[11]),
                         __fadd_rn(w[7], w[15]));
    return __fadd_rn(__fadd_rn(A0, A2), __fadd_rn(A1, A3));
}

__global__ __launch_bounds__(BLOCK_T)
void TsCv_29257317220818_kernel(const float* __restrict__ x,
                                float* __restrict__ out,
                                int n_rows)
{
    __shared__ float4 buf[2][VEC_PER_ROW];   // 2 x 16 KB

    const int tid  = threadIdx.x;
    const int row0 = blockIdx.x * ROWS_PER_CTA;

    // cp.async prefetch of one full row (4 x 16B per thread), one commit group.
    auto prefetch = [&](int i) {
        const int r = row0 + i;
        if (r < n_rows) {
            const float4* __restrict__ src4 =
                (const float4*)(x + (size_t)r * SEQ_LEN);
            float4* dstb = buf[i & 1];
            #pragma unroll
            for (int k = 0; k < VEC_PER_ROW / BLOCK_T; k++) {
                unsigned int saddr =
                    (unsigned int)__cvta_generic_to_shared(&dstb[tid + k * BLOCK_T]);
                asm volatile("cp.async.cg.shared.global [%0], [%1], 16;\n"
                             :: "r"(saddr), "l"(&src4[tid + k * BLOCK_T]));
            }
        }
        asm volatile("cp.async.commit_group;\n");
    };

    prefetch(0);

    for (int i = 0; i < ROWS_PER_CTA; i++) {
        const int r = row0 + i;

        if (i + 1 < ROWS_PER_CTA) {
            prefetch(i + 1);                              // overlap next row
            asm volatile("cp.async.wait_group 1;\n");     // current row ready
        } else {
            asm volatile("cp.async.wait_group 0;\n");
        }
        __syncthreads();

        if (r < n_rows) {
            const float* __restrict__ row = (const float*)buf[i & 1];
            float* __restrict__ dst = out + (size_t)r * OUT_LEN;

            for (int o = tid; o < OUT_LEN; o += BLOCK_T) {
                const int s = o * STRIDE_W;

                float w[MIN_W];
                #pragma unroll
                for (int k = 0; k < MIN_W; k++) w[k] = row[s + k];

                // Bit-exact reference sum (warp-shuffle tree order).
                const float sum  = warp_tree_sum20(w);
                const float mean = sum * 0.05f;

                // Sum of squares via FMA chain (relative accuracy only).
                float sumsq = 0.0f;
                #pragma unroll
                for (int k = 0; k < MIN_W; k++)
                    sumsq = fmaf(w[k], w[k], sumsq);

                const float ssd = fmaf(-sum, mean, sumsq);
                float var = ssd * (1.0f / (MIN_W - 1));
                var = fmaxf(var, 0.0f);

                float sd;
                asm("sqrt.approx.f32 %0, %1;" : "=f"(sd) : "f"(var));
                const float den = mean + EPS_CV;
                float cv = __fdividef(sd, den);
                if (isnan(cv)) cv = 0.0f;
                dst[o] = cv;
            }
        }
        __syncthreads();   // all compute on buf[i&1] done before it's refilled
    }
}

extern "C" void kernel_launch(void* const* d_in, const int* in_sizes, int n_in,
                              void* d_out, int out_size)
{
    const float* x = (const float*)d_in[0];
    float* out = (float*)d_out;

    const int n_rows = in_sizes[0] / SEQ_LEN;   // 64 * 256 = 16384
    const int grid = (n_rows + ROWS_PER_CTA - 1) / ROWS_PER_CTA;  // 2048
    TsCv_29257317220818_kernel<<<grid, BLOCK_T>>>(x, out, n_rows);
}

// round 13
// speedup vs baseline: 1.5245x; 1.0812x over previous
#include <cuda_runtime.h>
#include <cstdint>
#include <math.h>

// TsCv: sliding-window coefficient of variation.
// x: (64, 256, 4096) fp32  -> out: (64, 256, 816) fp32
// window = 20, stride = 5, var ddof=1, cv = std/(mean+1e-8), NaN -> 0.
//
// Numerics: ONLY the window SUM must bit-match the reference (XLA:GPU
// warp-shuffle tree, shfl_down 16,8,4,2,1 with zero lanes 20..31).
// Downstream math needs only relative accuracy (threshold 1e-3; measured
// margin 9.8e-8): sumsq identity + approx sqrt/div.
//
// Perf: R10 (cp.async double-buffer, 8 rows/CTA) hit 5.9TB/s / 74% DRAM.
// Remaining limiters: smem crossbar (20 LDS/window, L1=62%) and issue (74%).
// This version adds window-blocking: 272 threads x 3 consecutive windows
// from one 30-float span -> 10 LDS/window, straight-line per-row compute.

#define SEQ_LEN   4096
#define MIN_W     20
#define STRIDE_W  5
#define OUT_LEN   ((SEQ_LEN - MIN_W) / STRIDE_W + 1)   // 816
#define EPS_CV    1e-8f
#define BLOCK_T   272            // 816 / 3 windows per thread
#define WPT       3
#define SPAN      (MIN_W + (WPT - 1) * STRIDE_W)       // 30 floats
#define ROWS_PER_CTA 8
#define VEC_PER_ROW  (SEQ_LEN / 4)                     // 1024 float4

__device__ __forceinline__ float warp_tree_sum20(const float* __restrict__ w)
{
    float A0 = __fadd_rn(__fadd_rn(__fadd_rn(w[0], w[16]), w[8]),
                         __fadd_rn(w[4], w[12]));
    float A1 = __fadd_rn(__fadd_rn(__fadd_rn(w[1], w[17]), w[9]),
                         __fadd_rn(w[5], w[13]));
    float A2 = __fadd_rn(__fadd_rn(__fadd_rn(w[2], w[18]), w[10]),
                         __fadd_rn(w[6], w[14]));
    float A3 = __fadd_rn(__fadd_rn(__fadd_rn(w[3], w[19]), w[11]),
                         __fadd_rn(w[7], w[15]));
    return __fadd_rn(__fadd_rn(A0, A2), __fadd_rn(A1, A3));
}

__global__ __launch_bounds__(BLOCK_T, 5)
void TsCv_29257317220818_kernel(const float* __restrict__ x,
                                float* __restrict__ out,
                                int n_rows)
{
    __shared__ float4 buf[2][VEC_PER_ROW];   // 2 x 16 KB

    const int tid  = threadIdx.x;
    const int row0 = blockIdx.x * ROWS_PER_CTA;

    // cp.async prefetch of one full row, one commit group (strided over 272).
    auto prefetch = [&](int i) {
        const int r = row0 + i;
        if (r < n_rows) {
            const float4* __restrict__ src4 =
                (const float4*)(x + (size_t)r * SEQ_LEN);
            float4* dstb = buf[i & 1];
            for (int k = tid; k < VEC_PER_ROW; k += BLOCK_T) {
                unsigned int saddr =
                    (unsigned int)__cvta_generic_to_shared(&dstb[k]);
                asm volatile("cp.async.cg.shared.global [%0], [%1], 16;\n"
                             :: "r"(saddr), "l"(&src4[k]));
            }
        }
        asm volatile("cp.async.commit_group;\n");
    };

    prefetch(0);

    for (int i = 0; i < ROWS_PER_CTA; i++) {
        const int r = row0 + i;

        if (i + 1 < ROWS_PER_CTA) {
            prefetch(i + 1);                              // overlap next row
            asm volatile("cp.async.wait_group 1;\n");     // current row ready
        } else {
            asm volatile("cp.async.wait_group 0;\n");
        }
        __syncthreads();

        if (r < n_rows) {
            const float* __restrict__ row = (const float*)buf[i & 1];
            // thread t -> windows [3t, 3t+3), span of 30 floats at 15t.
            const int o0 = tid * WPT;                     // 0..813
            const int s0 = o0 * STRIDE_W;                 // 15 * tid

            float w[SPAN];
            #pragma unroll
            for (int k = 0; k < SPAN; k++) w[k] = row[s0 + k];

            float* __restrict__ dst = out + (size_t)r * OUT_LEN + o0;

            #pragma unroll
            for (int j = 0; j < WPT; j++) {
                const float* ww = w + j * STRIDE_W;

                // Bit-exact reference sum (warp-shuffle tree order).
                const float sum  = warp_tree_sum20(ww);
                const float mean = sum * 0.05f;

                // Sum of squares via FMA chain (relative accuracy only).
                float sumsq = 0.0f;
                #pragma unroll
                for (int k = 0; k < MIN_W; k++)
                    sumsq = fmaf(ww[k], ww[k], sumsq);

                const float ssd = fmaf(-sum, mean, sumsq);
                float var = ssd * (1.0f / (MIN_W - 1));
                var = fmaxf(var, 0.0f);

                float sd;
                asm("sqrt.approx.f32 %0, %1;" : "=f"(sd) : "f"(var));
                const float den = mean + EPS_CV;
                float cv = __fdividef(sd, den);
                if (isnan(cv)) cv = 0.0f;
                dst[j] = cv;
            }
        }
        __syncthreads();   // all compute on buf[i&1] done before it's refilled
    }
}

extern "C" void kernel_launch(void* const* d_in, const int* in_sizes, int n_in,
                              void* d_out, int out_size)
{
    const float* x = (const float*)d_in[0];
    float* out = (float*)d_out;

    const int n_rows = in_sizes[0] / SEQ_LEN;   // 64 * 256 = 16384
    const int grid = (n_rows + ROWS_PER_CTA - 1) / ROWS_PER_CTA;  // 2048
    TsCv_29257317220818_kernel<<<grid, BLOCK_T>>>(x, out, n_rows);
}

// round 15
// speedup vs baseline: 1.5337x; 1.0060x over previous
#include <cuda_runtime.h>
#include <cstdint>
#include <math.h>

// TsCv: sliding-window coefficient of variation.
// x: (64, 256, 4096) fp32  -> out: (64, 256, 816) fp32
// window = 20, stride = 5, var ddof=1, cv = std/(mean+1e-8), NaN -> 0.
//
// Numerics: ONLY the window SUM must bit-match the reference (XLA:GPU
// warp-shuffle tree, shfl_down 16,8,4,2,1 with zero lanes 20..31).
// Downstream math needs only relative accuracy (threshold 1e-3; measured
// margin ~1e-7): chunked sumsq identity + approx sqrt/div.
//
// Perf history: R10 cp.async double-buffer -> 5.9TB/s; R12 window-blocking
// (WPT=3) -> 53.6us, issue=71.5% co-limiting. This version: WPT=4 so the
// span base (20t words) is 16B-aligned -> 9x LDS.128 (conflict-free) instead
// of 30x LDS.32, chunk-shared sum-of-squares (47 ops vs 80), and one STG.128
// per thread. ~29% fewer issue slots per window.

#define SEQ_LEN   4096
#define MIN_W     20
#define STRIDE_W  5
#define OUT_LEN   ((SEQ_LEN - MIN_W) / STRIDE_W + 1)   // 816
#define EPS_CV    1e-8f
#define WPT       4
#define N_WORK    (OUT_LEN / WPT)                      // 204 compute threads
#define BLOCK_T   224                                  // 7 warps
#define SPAN_W    (MIN_W + (WPT - 1) * STRIDE_W)       // 35 words
#define SPAN_V4   9                                    // 36 words loaded
#define N_CHUNK   (SPAN_W / STRIDE_W)                  // 7 chunks of 5
#define ROWS_PER_CTA 8
#define VEC_PER_ROW  (SEQ_LEN / 4)                     // 1024 float4

__device__ __forceinline__ float warp_tree_sum20(const float* __restrict__ w)
{
    float A0 = __fadd_rn(__fadd_rn(__fadd_rn(w[0], w[16]), w[8]),
                         __fadd_rn(w[4], w[12]));
    float A1 = __fadd_rn(__fadd_rn(__fadd_rn(w[1], w[17]), w[9]),
                         __fadd_rn(w[5], w[13]));
    float A2 = __fadd_rn(__fadd_rn(__fadd_rn(w[2], w[18]), w[10]),
                         __fadd_rn(w[6], w[14]));
    float A3 = __fadd_rn(__fadd_rn(__fadd_rn(w[3], w[19]), w[11]),
                         __fadd_rn(w[7], w[15]));
    return __fadd_rn(__fadd_rn(A0, A2), __fadd_rn(A1, A3));
}

__global__ __launch_bounds__(BLOCK_T, 5)
void TsCv_29257317220818_kernel(const float* __restrict__ x,
                                float* __restrict__ out,
                                int n_rows)
{
    __shared__ float4 buf[2][VEC_PER_ROW];   // 2 x 16 KB

    const int tid  = threadIdx.x;
    const int row0 = blockIdx.x * ROWS_PER_CTA;

    // cp.async prefetch of one full row, one commit group (all 224 threads).
    auto prefetch = [&](int i) {
        const int r = row0 + i;
        if (r < n_rows) {
            const float4* __restrict__ src4 =
                (const float4*)(x + (size_t)r * SEQ_LEN);
            float4* dstb = buf[i & 1];
            for (int k = tid; k < VEC_PER_ROW; k += BLOCK_T) {
                unsigned int saddr =
                    (unsigned int)__cvta_generic_to_shared(&dstb[k]);
                asm volatile("cp.async.cg.shared.global [%0], [%1], 16;\n"
                             :: "r"(saddr), "l"(&src4[k]));
            }
        }
        asm volatile("cp.async.commit_group;\n");
    };

    prefetch(0);

    for (int i = 0; i < ROWS_PER_CTA; i++) {
        const int r = row0 + i;

        if (i + 1 < ROWS_PER_CTA) {
            prefetch(i + 1);                              // overlap next row
            asm volatile("cp.async.wait_group 1;\n");     // current row ready
        } else {
            asm volatile("cp.async.wait_group 0;\n");
        }
        __syncthreads();

        if (r < n_rows && tid < N_WORK) {
            const float4* __restrict__ rowv = buf[i & 1];
            // thread t -> windows [4t, 4t+4), span words [20t, 20t+35).
            const int o0 = tid * WPT;                     // 0..812
            const int v0 = tid * (WPT * STRIDE_W) / 4;    // 5t, float4 index

            float w[SPAN_V4 * 4];                         // 36 floats
            #pragma unroll
            for (int k = 0; k < SPAN_V4; k++) {
                float4 v = rowv[v0 + k];                  // LDS.128, no conflicts
                w[4 * k + 0] = v.x;
                w[4 * k + 1] = v.y;
                w[4 * k + 2] = v.z;
                w[4 * k + 3] = v.w;
            }

            // Chunked sum-of-squares: S[c] = sum_{i<5} w[5c+i]^2
            float S[N_CHUNK];
            #pragma unroll
            for (int c = 0; c < N_CHUNK; c++) {
                float s = __fmul_rn(w[5 * c], w[5 * c]);
                #pragma unroll
                for (int q = 1; q < STRIDE_W; q++)
                    s = fmaf(w[5 * c + q], w[5 * c + q], s);
                S[c] = s;
            }

            float4 res;
            float* resp = (float*)&res;
            #pragma unroll
            for (int j = 0; j < WPT; j++) {
                const float* ww = w + j * STRIDE_W;

                // Bit-exact reference sum (warp-shuffle tree order).
                const float sum  = warp_tree_sum20(ww);
                const float mean = sum * 0.05f;

                const float sumsq = __fadd_rn(__fadd_rn(S[j], S[j + 1]),
                                              __fadd_rn(S[j + 2], S[j + 3]));
                const float ssd = fmaf(-sum, mean, sumsq);
                float var = ssd * (1.0f / (MIN_W - 1));
                var = fmaxf(var, 0.0f);

                float sd;
                asm("sqrt.approx.f32 %0, %1;" : "=f"(sd) : "f"(var));
                const float den = mean + EPS_CV;
                float cv = __fdividef(sd, den);
                if (isnan(cv)) cv = 0.0f;
                resp[j] = cv;
            }

            // One 16B store: row base 3264B and o0=4t are both 16B-aligned.
            *(float4*)(out + (size_t)r * OUT_LEN + o0) = res;
        }
        __syncthreads();   // all compute on buf[i&1] done before it's refilled
    }
}

extern "C" void kernel_launch(void* const* d_in, const int* in_sizes, int n_in,
                              void* d_out, int out_size)
{
    const float* x = (const float*)d_in[0];
    float* out = (float*)d_out;

    const int n_rows = in_sizes[0] / SEQ_LEN;   // 64 * 256 = 16384
    const int grid = (n_rows + ROWS_PER_CTA - 1) / ROWS_PER_CTA;  // 2048
    TsCv_29257317220818_kernel<<<grid, BLOCK_T>>>(x, out, n_rows);
}